// round 2
// baseline (speedup 1.0000x reference)
#include <cuda_runtime.h>
#include <math.h>

#define NTOK 4096
#define DIM  1024
#define FF   4096
#define NG   4
#define NE   4
#define NEXP 16

#define BM 128
#define BN 128
#define BK 16

// Scratch (device globals: allocation-free per harness rules)
__device__ float g_h[(size_t)NTOK * 2 * FF];    // hidden activations per (token,slot)  134MB
__device__ float g_o[(size_t)NTOK * 2 * DIM];   // unweighted FFN outputs per slot      33.5MB
__device__ int   g_list[NEXP * NTOK];           // per-expert compacted (token*2+slot)
__device__ float g_w[NTOK * 2];                 // combine weights per slot
__device__ int   g_cnt[NEXP];                   // per-expert token counts
__device__ float g_tokent[NTOK];                // per-token entropy

__global__ void init_kernel() {
    if (threadIdx.x < NEXP) g_cnt[threadIdx.x] = 0;
}

// One warp per token: 4 group logits + 16 expert logits, top-2 groups,
// top-1 expert per group, softmax combine weights, entropy.
__global__ void routing_kernel(const float* __restrict__ x,
                               const float* __restrict__ Wg,
                               const float* __restrict__ We,
                               float* __restrict__ out) {
    int warp = (blockIdx.x * blockDim.x + threadIdx.x) >> 5;
    int lane = threadIdx.x & 31;
    if (warp >= NTOK) return;
    const float* xr = x + (size_t)warp * DIM;

    float acc[20];
#pragma unroll
    for (int i = 0; i < 20; i++) acc[i] = 0.f;

    for (int d = lane; d < DIM; d += 32) {
        float xv = xr[d];
#pragma unroll
        for (int g = 0; g < NG; g++) acc[g] += xv * Wg[g * DIM + d];
#pragma unroll
        for (int ge = 0; ge < NEXP; ge++) acc[4 + ge] += xv * We[ge * DIM + d];
    }
#pragma unroll
    for (int i = 0; i < 20; i++) {
#pragma unroll
        for (int o = 16; o > 0; o >>= 1)
            acc[i] += __shfl_xor_sync(0xffffffff, acc[i], o);
    }

    if (lane == 0) {
        float gl[4] = {acc[0], acc[1], acc[2], acc[3]};
        float* glo = out + (size_t)NTOK * DIM + (size_t)warp * 4;
        for (int g = 0; g < 4; g++) glo[g] = gl[g];

        // entropy of softmax over all 4 groups
        float m = gl[0];
        for (int g = 1; g < 4; g++) m = fmaxf(m, gl[g]);
        float se = 0.f;
        for (int g = 0; g < 4; g++) se += expf(gl[g] - m);
        float lse = m + logf(se);
        float ent = 0.f;
        for (int g = 0; g < 4; g++) { float lp = gl[g] - lse; ent -= expf(lp) * lp; }
        g_tokent[warp] = ent;

        // top-2 groups (stable: lower index wins ties, matching lax.top_k)
        int g0 = 0;
        for (int g = 1; g < 4; g++) if (gl[g] > gl[g0]) g0 = g;
        int g1 = -1;
        for (int g = 0; g < 4; g++) {
            if (g == g0) continue;
            if (g1 < 0 || gl[g] > gl[g1]) g1 = g;
        }
        // softmax over the two selected logits (gl[g0] >= gl[g1])
        float e1 = expf(gl[g1] - gl[g0]);
        float inv = 1.f / (1.f + e1);
        float w0 = inv, w1 = e1 * inv;

        // top-1 expert within each selected group (KE=1 -> ew = 1)
        int e0 = 0;
        {
            const float* el = &acc[4 + g0 * 4];
            for (int e = 1; e < 4; e++) if (el[e] > el[e0]) e0 = e;
        }
        int ex1 = 0;
        {
            const float* el = &acc[4 + g1 * 4];
            for (int e = 1; e < 4; e++) if (el[e] > el[ex1]) ex1 = e;
        }
        int ge0 = g0 * 4 + e0, ge1 = g1 * 4 + ex1;
        int p0 = atomicAdd(&g_cnt[ge0], 1);
        g_list[ge0 * NTOK + p0] = warp * 2;
        int p1 = atomicAdd(&g_cnt[ge1], 1);
        g_list[ge1 * NTOK + p1] = warp * 2 + 1;
        g_w[warp * 2]     = w0;
        g_w[warp * 2 + 1] = w1;
    }
}

__device__ __forceinline__ float gelu_exact(float v) {
    return 0.5f * v * (1.f + erff(v * 0.70710678118654752f));
}

// Up-proj grouped GEMM: H[m, f] = gelu( sum_d X[tok(m), d] * W1[e, f, d] )
__global__ __launch_bounds__(256) void up_kernel(const float* __restrict__ x,
                                                 const float* __restrict__ W1) {
    int expert = blockIdx.z;
    int cnt = g_cnt[expert];
    int m0 = blockIdx.y * BM;
    if (m0 >= cnt) return;
    int n0 = blockIdx.x * BN;
    const float* Bp = W1 + (size_t)expert * FF * DIM;

    __shared__ float As[BK][BM];
    __shared__ float Bs[BK][BN];
    __shared__ int toks[BM];
    int tid = threadIdx.x;
    if (tid < BM) {
        int m = m0 + tid;
        toks[tid] = g_list[expert * NTOK + (m < cnt ? m : 0)];
    }
    __syncthreads();

    float acc[8][8];
#pragma unroll
    for (int i = 0; i < 8; i++)
#pragma unroll
        for (int j = 0; j < 8; j++) acc[i][j] = 0.f;

    int tm = (tid >> 4) * 8;
    int tn = (tid & 15) * 8;

    for (int k0 = 0; k0 < DIM; k0 += BK) {
#pragma unroll
        for (int i = 0; i < 2; i++) {
            int idx = tid + i * 256;
            int row = idx >> 2;
            int k4  = (idx & 3) * 4;
            const float4 va = *(const float4*)(x + (size_t)(toks[row] >> 1) * DIM + k0 + k4);
            As[k4 + 0][row] = va.x; As[k4 + 1][row] = va.y;
            As[k4 + 2][row] = va.z; As[k4 + 3][row] = va.w;
            const float4 vb = *(const float4*)(Bp + (size_t)(n0 + row) * DIM + k0 + k4);
            Bs[k4 + 0][row] = vb.x; Bs[k4 + 1][row] = vb.y;
            Bs[k4 + 2][row] = vb.z; Bs[k4 + 3][row] = vb.w;
        }
        __syncthreads();
#pragma unroll
        for (int k = 0; k < BK; k++) {
            float a[8], b[8];
            *(float4*)&a[0] = *(const float4*)&As[k][tm];
            *(float4*)&a[4] = *(const float4*)&As[k][tm + 4];
            *(float4*)&b[0] = *(const float4*)&Bs[k][tn];
            *(float4*)&b[4] = *(const float4*)&Bs[k][tn + 4];
#pragma unroll
            for (int i = 0; i < 8; i++)
#pragma unroll
                for (int j = 0; j < 8; j++) acc[i][j] += a[i] * b[j];
        }
        __syncthreads();
    }

#pragma unroll
    for (int i = 0; i < 8; i++) {
        int rl = tm + i;
        if (m0 + rl < cnt) {
            float* dst = g_h + (size_t)toks[rl] * FF + n0 + tn;
#pragma unroll
            for (int j = 0; j < 8; j++) dst[j] = gelu_exact(acc[i][j]);
        }
    }
}

// Down-proj grouped GEMM: O[m, d] = sum_f H[tok(m), f] * W2[e, d, f]
__global__ __launch_bounds__(256) void down_kernel(const float* __restrict__ W2) {
    int expert = blockIdx.z;
    int cnt = g_cnt[expert];
    int m0 = blockIdx.y * BM;
    if (m0 >= cnt) return;
    int n0 = blockIdx.x * BN;
    const float* Bp = W2 + (size_t)expert * DIM * FF;

    __shared__ float As[BK][BM];
    __shared__ float Bs[BK][BN];
    __shared__ int toks[BM];
    int tid = threadIdx.x;
    if (tid < BM) {
        int m = m0 + tid;
        toks[tid] = g_list[expert * NTOK + (m < cnt ? m : 0)];
    }
    __syncthreads();

    float acc[8][8];
#pragma unroll
    for (int i = 0; i < 8; i++)
#pragma unroll
        for (int j = 0; j < 8; j++) acc[i][j] = 0.f;

    int tm = (tid >> 4) * 8;
    int tn = (tid & 15) * 8;

    for (int k0 = 0; k0 < FF; k0 += BK) {
#pragma unroll
        for (int i = 0; i < 2; i++) {
            int idx = tid + i * 256;
            int row = idx >> 2;
            int k4  = (idx & 3) * 4;
            const float4 va = *(const float4*)(g_h + (size_t)toks[row] * FF + k0 + k4);
            As[k4 + 0][row] = va.x; As[k4 + 1][row] = va.y;
            As[k4 + 2][row] = va.z; As[k4 + 3][row] = va.w;
            const float4 vb = *(const float4*)(Bp + (size_t)(n0 + row) * FF + k0 + k4);
            Bs[k4 + 0][row] = vb.x; Bs[k4 + 1][row] = vb.y;
            Bs[k4 + 2][row] = vb.z; Bs[k4 + 3][row] = vb.w;
        }
        __syncthreads();
#pragma unroll
        for (int k = 0; k < BK; k++) {
            float a[8], b[8];
            *(float4*)&a[0] = *(const float4*)&As[k][tm];
            *(float4*)&a[4] = *(const float4*)&As[k][tm + 4];
            *(float4*)&b[0] = *(const float4*)&Bs[k][tn];
            *(float4*)&b[4] = *(const float4*)&Bs[k][tn + 4];
#pragma unroll
            for (int i = 0; i < 8; i++)
#pragma unroll
                for (int j = 0; j < 8; j++) acc[i][j] += a[i] * b[j];
        }
        __syncthreads();
    }

#pragma unroll
    for (int i = 0; i < 8; i++) {
        int rl = tm + i;
        if (m0 + rl < cnt) {
            float* dst = g_o + (size_t)toks[rl] * DIM + n0 + tn;
#pragma unroll
            for (int j = 0; j < 8; j++) dst[j] = acc[i][j];
        }
    }
}

// out[n] = w0 * slot0[n] + w1 * slot1[n]
__global__ void combine_kernel(float* __restrict__ out) {
    int i = blockIdx.x * blockDim.x + threadIdx.x;
    if (i >= NTOK * DIM / 4) return;
    int n  = i / (DIM / 4);
    int d4 = i % (DIM / 4);
    const float4* o4 = (const float4*)g_o;
    float4 a = o4[(size_t)(2 * n) * (DIM / 4) + d4];
    float4 b = o4[(size_t)(2 * n + 1) * (DIM / 4) + d4];
    float w0 = g_w[2 * n], w1 = g_w[2 * n + 1];
    float4 r;
    r.x = w0 * a.x + w1 * b.x;
    r.y = w0 * a.y + w1 * b.y;
    r.z = w0 * a.z + w1 * b.z;
    r.w = w0 * a.w + w1 * b.w;
    ((float4*)out)[i] = r;
}

// Deterministic single-block mean-entropy reduction
__global__ void entropy_kernel(float* __restrict__ out) {
    __shared__ float s[256];
    float sum = 0.f;
    for (int i = threadIdx.x; i < NTOK; i += 256) sum += g_tokent[i];
    s[threadIdx.x] = sum;
    __syncthreads();
    for (int o = 128; o > 0; o >>= 1) {
        if (threadIdx.x < o) s[threadIdx.x] += s[threadIdx.x + o];
        __syncthreads();
    }
    if (threadIdx.x == 0)
        out[(size_t)NTOK * DIM + (size_t)NTOK * 4] = s[0] / (float)NTOK;
}

extern "C" void kernel_launch(void* const* d_in, const int* in_sizes, int n_in,
                              void* d_out, int out_size) {
    const float* x  = (const float*)d_in[0];
    const float* Wg = (const float*)d_in[1];
    const float* We = (const float*)d_in[2];
    const float* W1 = (const float*)d_in[3];
    const float* W2 = (const float*)d_in[4];
    float* out = (float*)d_out;

    init_kernel<<<1, 32>>>();
    routing_kernel<<<NTOK / 8, 256>>>(x, Wg, We, out);
    dim3 gu(FF / BN, NTOK / BM, NEXP);
    up_kernel<<<gu, 256>>>(x, W1);
    dim3 gd(DIM / BN, NTOK / BM, NEXP);
    down_kernel<<<gd, 256>>>(W2);
    combine_kernel<<<(NTOK * DIM / 4) / 256, 256>>>(out);
    entropy_kernel<<<1, 256>>>(out);
}

// round 16
// speedup vs baseline: 1.5461x; 1.5461x over previous
#include <cuda_runtime.h>
#include <cuda_bf16.h>
#include <math.h>
#include <stdint.h>

#define NTOK 4096
#define DIM  1024
#define FF   4096
#define NEXP 16

#define BMT 128
#define BNT 128
#define BKT 32           // K chunk (fp32 elements)

// ---- scratch (device globals; allocation-free) ----
__device__ float g_h[(size_t)NTOK * 2 * FF];
__device__ float g_o[(size_t)NTOK * 2 * DIM];
__device__ int   g_list[NEXP * NTOK];
__device__ float g_w[NTOK * 2];
__device__ int   g_cnt[NEXP];
__device__ float g_tokent[NTOK];

__device__ __forceinline__ uint32_t smem_u32(const void* p) {
    uint32_t a;
    asm("{ .reg .u64 t; cvta.to.shared.u64 t, %1; cvt.u32.u64 %0, t; }" : "=r"(a) : "l"(p));
    return a;
}
__device__ __forceinline__ void ldsm_x4(uint32_t* r, uint32_t addr) {
    asm volatile("ldmatrix.sync.aligned.m8n8.x4.shared.b16 {%0,%1,%2,%3}, [%4];"
                 : "=r"(r[0]), "=r"(r[1]), "=r"(r[2]), "=r"(r[3]) : "r"(addr));
}
__device__ __forceinline__ void ldsm_x2(uint32_t* r, uint32_t addr) {
    asm volatile("ldmatrix.sync.aligned.m8n8.x2.shared.b16 {%0,%1}, [%2];"
                 : "=r"(r[0]), "=r"(r[1]) : "r"(addr));
}
__device__ __forceinline__ void mma_bf16(float* c, const uint32_t* a, const uint32_t* b) {
    asm volatile("mma.sync.aligned.m16n8k16.row.col.f32.bf16.bf16.f32 "
                 "{%0,%1,%2,%3}, {%4,%5,%6,%7}, {%8,%9}, {%0,%1,%2,%3};"
                 : "+f"(c[0]), "+f"(c[1]), "+f"(c[2]), "+f"(c[3])
                 : "r"(a[0]), "r"(a[1]), "r"(a[2]), "r"(a[3]), "r"(b[0]), "r"(b[1]));
}
__device__ __forceinline__ void sts8(uint32_t addr, uint2 v) {
    asm volatile("st.shared.v2.b32 [%0], {%1, %2};" :: "r"(addr), "r"(v.x), "r"(v.y) : "memory");
}
__device__ __forceinline__ void cvt4(float4 v, uint2& hi, uint2& lo) {
    __nv_bfloat16 h0 = __float2bfloat16_rn(v.x);
    __nv_bfloat16 h1 = __float2bfloat16_rn(v.y);
    __nv_bfloat16 h2 = __float2bfloat16_rn(v.z);
    __nv_bfloat16 h3 = __float2bfloat16_rn(v.w);
    __nv_bfloat16 l0 = __float2bfloat16_rn(v.x - __bfloat162float(h0));
    __nv_bfloat16 l1 = __float2bfloat16_rn(v.y - __bfloat162float(h1));
    __nv_bfloat16 l2 = __float2bfloat16_rn(v.z - __bfloat162float(h2));
    __nv_bfloat16 l3 = __float2bfloat16_rn(v.w - __bfloat162float(h3));
    hi.x = (uint32_t)__bfloat16_as_ushort(h0) | ((uint32_t)__bfloat16_as_ushort(h1) << 16);
    hi.y = (uint32_t)__bfloat16_as_ushort(h2) | ((uint32_t)__bfloat16_as_ushort(h3) << 16);
    lo.x = (uint32_t)__bfloat16_as_ushort(l0) | ((uint32_t)__bfloat16_as_ushort(l1) << 16);
    lo.y = (uint32_t)__bfloat16_as_ushort(l2) | ((uint32_t)__bfloat16_as_ushort(l3) << 16);
}
__device__ __forceinline__ float gelu_exact(float v) {
    return 0.5f * v * (1.f + erff(v * 0.70710678118654752f));
}

// smem layout (bytes): toks[128] @0 ; buffers @1024
// per buffer: Ahi(128*80) Alo Bhi Blo = 4*10240 = 40960 ; 2 buffers
#define ROWB      80                       // 32 bf16 (64B) + 16B pad: ldmatrix conflict-free
#define TILEB     (128 * ROWB)             // 10240
#define BUFSZ     (4 * TILEB)              // 40960
#define OFF_BUF   1024
#define SMEM_BYTES (OFF_BUF + 2 * BUFSZ)   // ~83 KB

// ============ split-bf16 mma.sync grouped GEMM ============
// D[m, n] = sum_k A[row(m), k] * W[e, n, k]  (GELU on output if UP)
template<bool UP>
__global__ void __launch_bounds__(256, 1) ffn_gemm(const float* __restrict__ Asrc,
                                                   const float* __restrict__ W,
                                                   float* __restrict__ Dst) {
    constexpr int KTOT = UP ? DIM : FF;
    constexpr int NOUT = UP ? FF : DIM;
    constexpr int KCH  = KTOT / BKT;

    int expert = blockIdx.z;
    int cnt = g_cnt[expert];
    int m0 = blockIdx.y * BMT;
    if (m0 >= cnt) return;
    int n0 = blockIdx.x * BNT;

    extern __shared__ char smem[];
    uint32_t sb = smem_u32(smem);
    int* toks = (int*)smem;
    int tid = threadIdx.x;

    if (tid < BMT) {
        int m = m0 + tid;
        toks[tid] = g_list[expert * NTOK + (m < cnt ? m : cnt - 1)];
    }
    __syncthreads();

    // -------- loader assignment: threads 0-127 -> A rows, 128-255 -> B rows
    bool isA = tid < 128;
    int r = tid & 127;
    const float* src;
    if (isA) {
        int t = toks[r];
        src = Asrc + (size_t)(UP ? (t >> 1) : t) * KTOT;
    } else {
        src = W + (size_t)expert * ((size_t)NOUT * KTOT) + (size_t)(n0 + r) * KTOT;
    }
    uint32_t hi_base = sb + OFF_BUF + (isA ? 0 : 2 * TILEB) + (uint32_t)r * ROWB;

    int lane = tid & 31, wid = tid >> 5;
    int wm = (wid >> 2) * 64, wn = (wid & 3) * 32;
    uint32_t a_off = (uint32_t)(wm + (lane & 15)) * ROWB + (uint32_t)((lane >> 4) * 16);
    uint32_t b_off = (uint32_t)(wn + (lane & 7)) * ROWB + (uint32_t)(((lane >> 3) & 1) * 16);

    float c[4][4][4];
#pragma unroll
    for (int i = 0; i < 4; i++)
#pragma unroll
        for (int j = 0; j < 4; j++)
#pragma unroll
            for (int q = 0; q < 4; q++) c[i][j][q] = 0.f;

    float4 st[8];
    // prologue: chunk 0
#pragma unroll
    for (int i = 0; i < 8; i++) st[i] = ((const float4*)src)[i];
    {
        uint32_t base = hi_base;  // buffer 0
#pragma unroll
        for (int i = 0; i < 8; i++) {
            uint2 hi, lo;
            cvt4(st[i], hi, lo);
            sts8(base + i * 8, hi);
            sts8(base + TILEB + i * 8, lo);
        }
    }
    __syncthreads();

    for (int ch = 0; ch < KCH; ch++) {
        if (ch + 1 < KCH) {
            const float4* s4 = (const float4*)(src + (ch + 1) * BKT);
#pragma unroll
            for (int i = 0; i < 8; i++) st[i] = s4[i];
        }
        // compute on buffer ch&1
        uint32_t bufb = sb + OFF_BUF + (uint32_t)(ch & 1) * BUFSZ;
        uint32_t sA = bufb, sAlo = bufb + TILEB, sB = bufb + 2 * TILEB, sBlo = bufb + 3 * TILEB;
#pragma unroll
        for (int ks = 0; ks < 2; ks++) {
            uint32_t kb = ks * 32;  // 16 bf16 = 32 bytes
            uint32_t ah[4][4], al[4][4], bh[4][2], bl[4][2];
#pragma unroll
            for (int i = 0; i < 4; i++) ldsm_x4(ah[i], sA + a_off + (uint32_t)(i * 16) * ROWB + kb);
#pragma unroll
            for (int j = 0; j < 4; j++) ldsm_x2(bh[j], sB + b_off + (uint32_t)(j * 8) * ROWB + kb);
#pragma unroll
            for (int i = 0; i < 4; i++)
#pragma unroll
                for (int j = 0; j < 4; j++) mma_bf16(c[i][j], ah[i], bh[j]);
#pragma unroll
            for (int j = 0; j < 4; j++) ldsm_x2(bl[j], sBlo + b_off + (uint32_t)(j * 8) * ROWB + kb);
#pragma unroll
            for (int i = 0; i < 4; i++)
#pragma unroll
                for (int j = 0; j < 4; j++) mma_bf16(c[i][j], ah[i], bl[j]);
#pragma unroll
            for (int i = 0; i < 4; i++) ldsm_x4(al[i], sAlo + a_off + (uint32_t)(i * 16) * ROWB + kb);
#pragma unroll
            for (int i = 0; i < 4; i++)
#pragma unroll
                for (int j = 0; j < 4; j++) mma_bf16(c[i][j], al[i], bh[j]);
        }
        __syncthreads();
        if (ch + 1 < KCH) {
            uint32_t base = hi_base + (uint32_t)((ch + 1) & 1) * BUFSZ;
#pragma unroll
            for (int i = 0; i < 8; i++) {
                uint2 hi, lo;
                cvt4(st[i], hi, lo);
                sts8(base + i * 8, hi);
                sts8(base + TILEB + i * 8, lo);
            }
            __syncthreads();
        }
    }

    // -------- epilogue: accum regs -> global (GELU if UP)
#pragma unroll
    for (int i = 0; i < 4; i++) {
        int row0 = wm + i * 16 + (lane >> 2);
#pragma unroll
        for (int half = 0; half < 2; half++) {
            int mrow = row0 + half * 8;
            if (m0 + mrow < cnt) {
                float* drow = Dst + (size_t)toks[mrow] * NOUT + n0;
#pragma unroll
                for (int j = 0; j < 4; j++) {
                    float v0 = c[i][j][half * 2 + 0];
                    float v1 = c[i][j][half * 2 + 1];
                    if (UP) { v0 = gelu_exact(v0); v1 = gelu_exact(v1); }
                    int col = wn + j * 8 + (lane & 3) * 2;
                    ((float2*)(drow + col))[0] = make_float2(v0, v1);
                }
            }
        }
    }
}

// ===================== routing / combine / entropy =====================
__global__ void init_kernel() {
    if (threadIdx.x < NEXP) g_cnt[threadIdx.x] = 0;
}

__global__ void routing_kernel(const float* __restrict__ x,
                               const float* __restrict__ Wg,
                               const float* __restrict__ We,
                               float* __restrict__ out) {
    int warp = (blockIdx.x * blockDim.x + threadIdx.x) >> 5;
    int lane = threadIdx.x & 31;
    if (warp >= NTOK) return;
    const float* xr = x + (size_t)warp * DIM;

    float acc[20];
#pragma unroll
    for (int i = 0; i < 20; i++) acc[i] = 0.f;
    for (int d = lane; d < DIM; d += 32) {
        float xv = xr[d];
#pragma unroll
        for (int g = 0; g < 4; g++) acc[g] += xv * Wg[g * DIM + d];
#pragma unroll
        for (int ge = 0; ge < NEXP; ge++) acc[4 + ge] += xv * We[ge * DIM + d];
    }
#pragma unroll
    for (int i = 0; i < 20; i++)
#pragma unroll
        for (int o = 16; o > 0; o >>= 1)
            acc[i] += __shfl_xor_sync(0xffffffff, acc[i], o);

    if (lane == 0) {
        float gl[4] = {acc[0], acc[1], acc[2], acc[3]};
        float* glo = out + (size_t)NTOK * DIM + (size_t)warp * 4;
        for (int g = 0; g < 4; g++) glo[g] = gl[g];

        float m = gl[0];
        for (int g = 1; g < 4; g++) m = fmaxf(m, gl[g]);
        float se = 0.f;
        for (int g = 0; g < 4; g++) se += expf(gl[g] - m);
        float lse = m + logf(se);
        float ent = 0.f;
        for (int g = 0; g < 4; g++) { float lp = gl[g] - lse; ent -= expf(lp) * lp; }
        g_tokent[warp] = ent;

        int g0 = 0;
        for (int g = 1; g < 4; g++) if (gl[g] > gl[g0]) g0 = g;
        int g1 = -1;
        for (int g = 0; g < 4; g++) {
            if (g == g0) continue;
            if (g1 < 0 || gl[g] > gl[g1]) g1 = g;
        }
        float e1 = expf(gl[g1] - gl[g0]);
        float inv = 1.f / (1.f + e1);
        float w0 = inv, w1 = e1 * inv;

        int e0 = 0;
        { const float* el = &acc[4 + g0 * 4];
          for (int e = 1; e < 4; e++) if (el[e] > el[e0]) e0 = e; }
        int ex1 = 0;
        { const float* el = &acc[4 + g1 * 4];
          for (int e = 1; e < 4; e++) if (el[e] > el[ex1]) ex1 = e; }
        int ge0 = g0 * 4 + e0, ge1 = g1 * 4 + ex1;
        int p0 = atomicAdd(&g_cnt[ge0], 1);
        g_list[ge0 * NTOK + p0] = warp * 2;
        int p1 = atomicAdd(&g_cnt[ge1], 1);
        g_list[ge1 * NTOK + p1] = warp * 2 + 1;
        g_w[warp * 2] = w0;
        g_w[warp * 2 + 1] = w1;
    }
}

__global__ void combine_kernel(float* __restrict__ out) {
    int i = blockIdx.x * blockDim.x + threadIdx.x;
    if (i >= NTOK * DIM / 4) return;
    int n  = i / (DIM / 4);
    int d4 = i % (DIM / 4);
    const float4* o4 = (const float4*)g_o;
    float4 a = o4[(size_t)(2 * n) * (DIM / 4) + d4];
    float4 b = o4[(size_t)(2 * n + 1) * (DIM / 4) + d4];
    float w0 = g_w[2 * n], w1 = g_w[2 * n + 1];
    float4 rr;
    rr.x = w0 * a.x + w1 * b.x;
    rr.y = w0 * a.y + w1 * b.y;
    rr.z = w0 * a.z + w1 * b.z;
    rr.w = w0 * a.w + w1 * b.w;
    ((float4*)out)[i] = rr;
}

__global__ void entropy_kernel(float* __restrict__ out) {
    __shared__ float s[256];
    float sum = 0.f;
    for (int i = threadIdx.x; i < NTOK; i += 256) sum += g_tokent[i];
    s[threadIdx.x] = sum;
    __syncthreads();
    for (int o = 128; o > 0; o >>= 1) {
        if (threadIdx.x < o) s[threadIdx.x] += s[threadIdx.x + o];
        __syncthreads();
    }
    if (threadIdx.x == 0)
        out[(size_t)NTOK * DIM + (size_t)NTOK * 4] = s[0] / (float)NTOK;
}

extern "C" void kernel_launch(void* const* d_in, const int* in_sizes, int n_in,
                              void* d_out, int out_size) {
    const float* x  = (const float*)d_in[0];
    const float* Wg = (const float*)d_in[1];
    const float* We = (const float*)d_in[2];
    const float* W1 = (const float*)d_in[3];
    const float* W2 = (const float*)d_in[4];
    float* out = (float*)d_out;

    cudaFuncSetAttribute(ffn_gemm<true>, cudaFuncAttributeMaxDynamicSharedMemorySize, SMEM_BYTES);
    cudaFuncSetAttribute(ffn_gemm<false>, cudaFuncAttributeMaxDynamicSharedMemorySize, SMEM_BYTES);

    float* g_h_ptr;  cudaGetSymbolAddress((void**)&g_h_ptr, g_h);
    float* g_o_ptr;  cudaGetSymbolAddress((void**)&g_o_ptr, g_o);

    init_kernel<<<1, 32>>>();
    routing_kernel<<<NTOK / 8, 256>>>(x, Wg, We, out);

    dim3 gu(FF / BNT, NTOK / BMT, NEXP);
    ffn_gemm<true><<<gu, 256, SMEM_BYTES>>>(x, W1, g_h_ptr);

    dim3 gd(DIM / BNT, NTOK / BMT, NEXP);
    ffn_gemm<false><<<gd, 256, SMEM_BYTES>>>(g_h_ptr, W2, g_o_ptr);

    combine_kernel<<<(NTOK * DIM / 4) / 256, 256>>>(out);
    entropy_kernel<<<1, 256>>>(out);
}